// round 7
// baseline (speedup 1.0000x reference)
#include <cuda_runtime.h>
#include <cuda_bf16.h>
#include <cstdint>

// Problem constants
#define B_   16
#define SQ_  128
#define SV_  128
#define DQ_  512
#define DV_  512
#define U_   256

// ---------------------------------------------------------------------------
// Scratch (__device__ globals — no allocation APIs allowed)
// ---------------------------------------------------------------------------
__device__ float g_s1[B_ * SQ_ * U_];      // [2048][256]
__device__ float g_s2[B_ * SV_ * U_];      // [2048][256]
__device__ float g_score[B_ * SQ_ * SV_];  // [16][128][128]

// Fragment-native packed operands for the mma.sync GEMMs.
__device__ uint4 g_Ahp[2][128 * 32 * 32];
__device__ uint4 g_Alp[2][128 * 32 * 32];
__device__ uint4 g_Wp [2][ 32 * 32 * 32];

// ---------------------------------------------------------------------------
// Helpers
// ---------------------------------------------------------------------------
__device__ __forceinline__ uint32_t smem_u32(const void* p) {
    uint32_t a;
    asm("{ .reg .u64 t; cvta.to.shared.u64 t, %1; cvt.u32.u64 %0, t; }"
        : "=r"(a) : "l"(p));
    return a;
}
__device__ __forceinline__ void cp_async16(uint32_t s, const void* g) {
    asm volatile("cp.async.cg.shared.global [%0], [%1], 16;" :: "r"(s), "l"(g));
}
#define CP_COMMIT()  asm volatile("cp.async.commit_group;" ::: "memory")
#define CP_WAIT0()   asm volatile("cp.async.wait_group 0;" ::: "memory")

// mma.sync m16n8k16 bf16 (row.col), fp32 accumulate — base sm_80+ feature.
__device__ __forceinline__ void mma_bf16(float* d, const uint32_t* a,
                                         uint32_t b0, uint32_t b1) {
    asm volatile(
        "mma.sync.aligned.m16n8k16.row.col.f32.bf16.bf16.f32 "
        "{%0,%1,%2,%3}, {%4,%5,%6,%7}, {%8,%9}, {%0,%1,%2,%3};"
        : "+f"(d[0]), "+f"(d[1]), "+f"(d[2]), "+f"(d[3])
        : "r"(a[0]), "r"(a[1]), "r"(a[2]), "r"(a[3]), "r"(b0), "r"(b1));
}

__device__ __forceinline__ uint32_t split_pack(float x0, float x1, uint32_t& lo_pack) {
    __nv_bfloat16 h0 = __float2bfloat16(x0);
    __nv_bfloat16 h1 = __float2bfloat16(x1);
    float r0 = x0 - __bfloat162float(h0);
    float r1 = x1 - __bfloat162float(h1);
    __nv_bfloat16 l0 = __float2bfloat16(r0);
    __nv_bfloat16 l1 = __float2bfloat16(r1);
    lo_pack = ((uint32_t)__bfloat16_as_ushort(l1) << 16) | __bfloat16_as_ushort(l0);
    return ((uint32_t)__bfloat16_as_ushort(h1) << 16) | __bfloat16_as_ushort(h0);
}

// ---------------------------------------------------------------------------
// Kernel 0: fp32 -> bf16 (hi, lo) split into fragment-native packed layouts.
// Each thread now produces COMPLETE uint4 fragments (16B contiguous stores).
// grid (512, 4): y=0 query, y=1 values, y=2 W1, y=3 W2 (W -> [n][k] fragments).
// ---------------------------------------------------------------------------
__global__ __launch_bounds__(256) void convert_kernel(
    const float* __restrict__ q, const float* __restrict__ v,
    const float* __restrict__ W1, const float* __restrict__ W2)
{
    const int z = blockIdx.y;
    const int j = blockIdx.x * 256 + threadIdx.x;

    if (z < 2) {
        // A fragments: j -> (rb, ks, lane). Thread covers rows {r0, r0+8},
        // k pairs {k0,k0+1} and {k0+8,k0+9}.
        const float* __restrict__ src = z ? v : q;       // [2048][512]
        const int rb   = j >> 10;            // 0..127
        const int ks   = (j >> 5) & 31;      // 0..31
        const int lane = j & 31;
        const int r0 = rb * 16 + (lane >> 2);
        const int k0 = ks * 16 + (lane & 3) * 2;

        float2 a00 = *(const float2*)&src[(size_t)r0 * 512 + k0];
        float2 a01 = *(const float2*)&src[(size_t)r0 * 512 + k0 + 8];
        float2 a10 = *(const float2*)&src[(size_t)(r0 + 8) * 512 + k0];
        float2 a11 = *(const float2*)&src[(size_t)(r0 + 8) * 512 + k0 + 8];

        uint4 hi, lo;
        hi.x = split_pack(a00.x, a00.y, lo.x);   // s0: row r0,   k0
        hi.y = split_pack(a10.x, a10.y, lo.y);   // s1: row r0+8, k0
        hi.z = split_pack(a01.x, a01.y, lo.z);   // s2: row r0,   k0+8
        hi.w = split_pack(a11.x, a11.y, lo.w);   // s3: row r0+8, k0+8
        g_Ahp[z][j] = hi;
        g_Alp[z][j] = lo;
    } else {
        // W fragments: j -> (nb, ks, lane). n fixed per thread.
        if (j >= 32 * 32 * 32) return;
        const float* __restrict__ src = (z == 3) ? W2 : W1;  // [512][256]
        const int nb   = j >> 10;            // 0..31
        const int ks   = (j >> 5) & 31;
        const int lane = j & 31;
        const int n  = nb * 8 + (lane >> 2);
        const int k0 = ks * 16 + (lane & 3) * 2;

        float w00 = src[(size_t)k0 * 256 + n];
        float w01 = src[(size_t)(k0 + 1) * 256 + n];
        float w10 = src[(size_t)(k0 + 8) * 256 + n];
        float w11 = src[(size_t)(k0 + 9) * 256 + n];

        uint4 f;
        uint32_t l0, l1;
        f.x = split_pack(w00, w01, l0);      // b0 hi
        f.y = split_pack(w10, w11, l1);      // b1 hi
        f.z = l0;                            // b0 lo
        f.w = l1;                            // b1 lo
        g_Wp[z - 2][j] = f;
    }
}

// ---------------------------------------------------------------------------
// Kernel A: tensor-core GEMM via mma.sync (bf16 hi/lo split, fp32 accum).
// C[2048,256] = A[2048,512] @ W[512,256] + bias, z=0 -> s1, z=1 -> s2.
// ---------------------------------------------------------------------------
__global__ __launch_bounds__(256) void gemm_mma_kernel(
    const float* __restrict__ b1, const float* __restrict__ b2)
{
    const int tid  = threadIdx.x;
    const int wid  = tid >> 5;
    const int lane = tid & 31;
    const int g    = lane >> 2;
    const int tg   = lane & 3;

    const int z  = blockIdx.z;
    const int m0 = blockIdx.y * 128;
    const int n0 = blockIdx.x * 64;

    const uint4* __restrict__ Ah = g_Ahp[z];
    const uint4* __restrict__ Al = g_Alp[z];
    const uint4* __restrict__ Bp = g_Wp[z];
    float* __restrict__ C            = z ? g_s2 : g_s1;
    const float* __restrict__ bias   = z ? b2 : b1;

    const int warp_m = wid & 3;
    const int warp_n = wid >> 2;
    const int rb0 = (m0 >> 4) + warp_m * 2;
    const int nb0 = (n0 >> 3) + warp_n * 4;

    float acc[2][4][4];
#pragma unroll
    for (int mt = 0; mt < 2; mt++)
#pragma unroll
        for (int nt = 0; nt < 4; nt++)
#pragma unroll
            for (int c = 0; c < 4; c++) acc[mt][nt][c] = 0.f;

#pragma unroll 2
    for (int ks = 0; ks < 32; ks++) {
        uint4 AH[2], AL[2], Bf[4];
#pragma unroll
        for (int mt = 0; mt < 2; mt++) {
            AH[mt] = Ah[((rb0 + mt) * 32 + ks) * 32 + lane];
            AL[mt] = Al[((rb0 + mt) * 32 + ks) * 32 + lane];
        }
#pragma unroll
        for (int nt = 0; nt < 4; nt++)
            Bf[nt] = Bp[((nb0 + nt) * 32 + ks) * 32 + lane];

#pragma unroll
        for (int mt = 0; mt < 2; mt++)
#pragma unroll
            for (int nt = 0; nt < 4; nt++) {
                mma_bf16(acc[mt][nt], (const uint32_t*)&AH[mt], Bf[nt].x, Bf[nt].y);
                mma_bf16(acc[mt][nt], (const uint32_t*)&AH[mt], Bf[nt].z, Bf[nt].w);
                mma_bf16(acc[mt][nt], (const uint32_t*)&AL[mt], Bf[nt].x, Bf[nt].y);
            }
    }

#pragma unroll
    for (int mt = 0; mt < 2; mt++) {
        const int row = m0 + warp_m * 32 + mt * 16 + g;
#pragma unroll
        for (int nt = 0; nt < 4; nt++) {
            const int col = n0 + warp_n * 32 + nt * 8 + tg * 2;
            const float2 bb = *(const float2*)&bias[col];
            float2 o0, o1;
            o0.x = acc[mt][nt][0] + bb.x;
            o0.y = acc[mt][nt][1] + bb.y;
            o1.x = acc[mt][nt][2] + bb.x;
            o1.y = acc[mt][nt][3] + bb.y;
            *(float2*)&C[(size_t)row * U_ + col]       = o0;
            *(float2*)&C[(size_t)(row + 8) * U_ + col] = o1;
        }
    }
}

// ---------------------------------------------------------------------------
// Kernel B: score[b,q,v] = Vb + sum_u tanh(s1[b,q,u] + s2[b,v,u]) * Vw[u]
// 16q x 16v tiles -> 1024 blocks (near-perfect wave balance on 148 SMs).
// ---------------------------------------------------------------------------
__device__ __forceinline__ float tanh_fast(float x) {
    float y;
    asm("tanh.approx.f32 %0, %1;" : "=f"(y) : "f"(x));
    return y;
}

__global__ __launch_bounds__(256) void score_kernel(
    const float* __restrict__ Vw, const float* __restrict__ Vb)
{
    __shared__ float sS1[16][65];
    __shared__ float sS2[16][65];
    __shared__ float sVw[64];

    const int tid = threadIdx.x;
    const int b   = blockIdx.z;
    const int q0  = blockIdx.y * 16;
    const int v0  = blockIdx.x * 16;

    const int tx = tid & 15;        // v
    const int ty = tid >> 4;        // q row

    float acc = 0.f;

    for (int u0 = 0; u0 < U_; u0 += 64) {
        {   // one float4 per thread per array: 16 rows x 64 u
            const int lr  = tid >> 4;
            const int lc4 = (tid & 15) << 2;
            float4 v1 = *(const float4*)&g_s1[((b * SQ_) + q0 + lr) * U_ + u0 + lc4];
            sS1[lr][lc4 + 0] = v1.x; sS1[lr][lc4 + 1] = v1.y;
            sS1[lr][lc4 + 2] = v1.z; sS1[lr][lc4 + 3] = v1.w;
            float4 v2 = *(const float4*)&g_s2[((b * SV_) + v0 + lr) * U_ + u0 + lc4];
            sS2[lr][lc4 + 0] = v2.x; sS2[lr][lc4 + 1] = v2.y;
            sS2[lr][lc4 + 2] = v2.z; sS2[lr][lc4 + 3] = v2.w;
        }
        if (tid < 64) sVw[tid] = Vw[u0 + tid];
        __syncthreads();

#pragma unroll 16
        for (int uu = 0; uu < 64; uu++) {
            float t = tanh_fast(sS1[ty][uu] + sS2[tx][uu]);
            acc = fmaf(t, sVw[uu], acc);
        }
        __syncthreads();
    }

    g_score[((b * SQ_) + q0 + ty) * SV_ + v0 + tx] = acc + Vb[0];
}

// ---------------------------------------------------------------------------
// Kernel C: fused softmax + context.
// Tile: 32 q x 128 d per block; grid (4 dtile, 4 qtile, 16 b) = 256 blocks.
// Phase 0: issue cp.async for values chunk 0.
// Phase 1: load score tile, in-block row softmax (warp = 4 rows), weights in
//          smem; d-tile 0 blocks also write out_w.
// Phase 2: context GEMM with cp.async double-buffered values chunks.
// ---------------------------------------------------------------------------
__global__ __launch_bounds__(256) void ctx_kernel(
    const float* __restrict__ values,
    float* __restrict__ out_w,
    float* __restrict__ out_ctx)
{
    __shared__ float sW[32][128];
    __shared__ float sV[2][32 * 128];

    const int tid = threadIdx.x;
    const int b   = blockIdx.z;
    const int q0  = blockIdx.y * 32;
    const int d0  = blockIdx.x * 128;

    const float* __restrict__ vsrc = values + (size_t)b * SV_ * DV_ + d0;
    const uint32_t svb = smem_u32(&sV[0][0]);

    // Phase 0: prefetch values chunk 0 (v rows 0..31).
#pragma unroll
    for (int k = 0; k < 4; k++) {
        const int idx = tid + k * 256;
        const int r   = idx >> 5;
        const int c4  = idx & 31;
        cp_async16(svb + (uint32_t)(r * 128 + c4 * 4) * 4,
                   vsrc + (size_t)r * DV_ + c4 * 4);
    }
    CP_COMMIT();

    // Phase 1: load score tile + softmax.
#pragma unroll
    for (int k = 0; k < 4; k++) {
        const int idx = tid + k * 256;
        const int r   = idx >> 5;
        const int c4  = idx & 31;
        float4 s = *(const float4*)&g_score[((b * SQ_) + q0 + r) * SV_ + (c4 << 2)];
        *(float4*)&sW[r][c4 << 2] = s;
    }
    __syncthreads();

    const int warp = tid >> 5;
    const int lane = tid & 31;
#pragma unroll
    for (int i = 0; i < 4; i++) {
        const int r = warp * 4 + i;
        float sc[4];
#pragma unroll
        for (int j = 0; j < 4; j++) sc[j] = sW[r][lane + 32 * j];
        float m = fmaxf(fmaxf(sc[0], sc[1]), fmaxf(sc[2], sc[3]));
#pragma unroll
        for (int o = 16; o > 0; o >>= 1)
            m = fmaxf(m, __shfl_xor_sync(0xFFFFFFFFu, m, o));
        float e[4], s = 0.f;
#pragma unroll
        for (int j = 0; j < 4; j++) { e[j] = __expf(sc[j] - m); s += e[j]; }
#pragma unroll
        for (int o = 16; o > 0; o >>= 1)
            s += __shfl_xor_sync(0xFFFFFFFFu, s, o);
        float inv = __fdividef(1.f, s);
#pragma unroll
        for (int j = 0; j < 4; j++) {
            float w = e[j] * inv;
            sW[r][lane + 32 * j] = w;
            if (blockIdx.x == 0)
                out_w[((b * SQ_) + q0 + r) * SV_ + lane + 32 * j] = w;
        }
    }

    // Phase 2: context.
    const int dg = tid & 31;
    const int qg = tid >> 5;

    float4 acc[4];
#pragma unroll
    for (int i = 0; i < 4; i++) acc[i] = make_float4(0.f, 0.f, 0.f, 0.f);

#pragma unroll
    for (int c = 0; c < 4; c++) {
        CP_WAIT0();
        __syncthreads();

        if (c < 3) {
            const uint32_t nb = svb + (uint32_t)(((c + 1) & 1) * 32 * 128) * 4;
            const float* gsrc = vsrc + (size_t)(c + 1) * 32 * DV_;
#pragma unroll
            for (int k = 0; k < 4; k++) {
                const int idx = tid + k * 256;
                const int r   = idx >> 5;
                const int c4  = idx & 31;
                cp_async16(nb + (uint32_t)(r * 128 + c4 * 4) * 4,
                           gsrc + (size_t)r * DV_ + c4 * 4);
            }
            CP_COMMIT();
        }

        const float* sv = &sV[c & 1][0];
#pragma unroll
        for (int v = 0; v < 32; v++) {
            float4 vv = *(const float4*)&sv[v * 128 + (dg << 2)];
            const int gv = c * 32 + v;
#pragma unroll
            for (int i = 0; i < 4; i++) {
                float w = sW[qg * 4 + i][gv];
                acc[i].x = fmaf(w, vv.x, acc[i].x);
                acc[i].y = fmaf(w, vv.y, acc[i].y);
                acc[i].z = fmaf(w, vv.z, acc[i].z);
                acc[i].w = fmaf(w, vv.w, acc[i].w);
            }
        }
        __syncthreads();
    }

#pragma unroll
    for (int i = 0; i < 4; i++) {
        const int q = q0 + qg * 4 + i;
        *(float4*)&out_ctx[((size_t)(b * SQ_) + q) * DV_ + d0 + (dg << 2)] = acc[i];
    }
}

// ---------------------------------------------------------------------------
extern "C" void kernel_launch(void* const* d_in, const int* in_sizes, int n_in,
                              void* d_out, int out_size)
{
    const float* query  = (const float*)d_in[0];
    const float* values = (const float*)d_in[1];
    const float* W1     = (const float*)d_in[2];
    const float* b1     = (const float*)d_in[3];
    const float* W2     = (const float*)d_in[4];
    const float* b2     = (const float*)d_in[5];
    const float* Vw     = (const float*)d_in[6];
    const float* Vb     = (const float*)d_in[7];

    float* out_ctx = (float*)d_out;                      // [16,128,512]
    float* out_w   = out_ctx + B_ * SQ_ * DV_;           // [16,128,128,1]

    // fp32 -> bf16 hi/lo split into fragment-native packed layouts
    convert_kernel<<<dim3(512, 4), 256>>>(query, values, W1, W2);

    // tensor-core GEMMs: s1 = q@W1+b1, s2 = v@W2+b2
    gemm_mma_kernel<<<dim3(4, 16, 2), 256>>>(b1, b2);

    // score = reduce_u tanh(s1+s2)*Vw + Vb
    score_kernel<<<dim3(8, 8, 16), 256>>>(Vw, Vb);

    // fused softmax + context
    ctx_kernel<<<dim3(4, 4, 16), 256>>>(values, out_w, out_ctx);
}

// round 8
// speedup vs baseline: 1.3794x; 1.3794x over previous
#include <cuda_runtime.h>
#include <cuda_bf16.h>
#include <cstdint>

// Problem constants
#define B_   16
#define SQ_  128
#define SV_  128
#define DQ_  512
#define DV_  512
#define U_   256

// ---------------------------------------------------------------------------
// Scratch (__device__ globals — no allocation APIs allowed)
// ---------------------------------------------------------------------------
__device__ float g_s1[B_ * SQ_ * U_];      // [2048][256]
__device__ float g_s2[B_ * SV_ * U_];      // [2048][256]
__device__ float g_score[B_ * SQ_ * SV_];  // [16][128][128]

// Fragment-native packed operands for the mma.sync GEMMs.
__device__ uint4 g_Ahp[2][128 * 32 * 32];
__device__ uint4 g_Alp[2][128 * 32 * 32];
__device__ uint4 g_Wp [2][ 32 * 32 * 32];

// ---------------------------------------------------------------------------
// Helpers
// ---------------------------------------------------------------------------
__device__ __forceinline__ uint32_t smem_u32(const void* p) {
    uint32_t a;
    asm("{ .reg .u64 t; cvta.to.shared.u64 t, %1; cvt.u32.u64 %0, t; }"
        : "=r"(a) : "l"(p));
    return a;
}
__device__ __forceinline__ void cp_async16(uint32_t s, const void* g) {
    asm volatile("cp.async.cg.shared.global [%0], [%1], 16;" :: "r"(s), "l"(g));
}
#define CP_COMMIT()  asm volatile("cp.async.commit_group;" ::: "memory")
#define CP_WAIT0()   asm volatile("cp.async.wait_group 0;" ::: "memory")

// mma.sync m16n8k16 bf16 (row.col), fp32 accumulate — base sm_80+ feature.
__device__ __forceinline__ void mma_bf16(float* d, const uint32_t* a,
                                         uint32_t b0, uint32_t b1) {
    asm volatile(
        "mma.sync.aligned.m16n8k16.row.col.f32.bf16.bf16.f32 "
        "{%0,%1,%2,%3}, {%4,%5,%6,%7}, {%8,%9}, {%0,%1,%2,%3};"
        : "+f"(d[0]), "+f"(d[1]), "+f"(d[2]), "+f"(d[3])
        : "r"(a[0]), "r"(a[1]), "r"(a[2]), "r"(a[3]), "r"(b0), "r"(b1));
}

__device__ __forceinline__ uint32_t split_pack(float x0, float x1, uint32_t& lo_pack) {
    __nv_bfloat16 h0 = __float2bfloat16(x0);
    __nv_bfloat16 h1 = __float2bfloat16(x1);
    float r0 = x0 - __bfloat162float(h0);
    float r1 = x1 - __bfloat162float(h1);
    __nv_bfloat16 l0 = __float2bfloat16(r0);
    __nv_bfloat16 l1 = __float2bfloat16(r1);
    lo_pack = ((uint32_t)__bfloat16_as_ushort(l1) << 16) | __bfloat16_as_ushort(l0);
    return ((uint32_t)__bfloat16_as_ushort(h1) << 16) | __bfloat16_as_ushort(h0);
}

// ---------------------------------------------------------------------------
// Kernel 0 (R6 version): fp32 -> bf16 (hi, lo) split into fragment layouts.
// grid (2048, 4): y=0 query, y=1 values, y=2 W1, y=3 W2.
// ---------------------------------------------------------------------------
__global__ __launch_bounds__(256) void convert_kernel(
    const float* __restrict__ q, const float* __restrict__ v,
    const float* __restrict__ W1, const float* __restrict__ W2)
{
    const int z = blockIdx.y;
    const int i = blockIdx.x * 256 + threadIdx.x;

    if (z < 2) {
        const float* src = z ? v : q;                  // [2048][512]
        uint32_t* dh = (uint32_t*)g_Ahp[z];
        uint32_t* dl = (uint32_t*)g_Alp[z];
        const int row = i >> 8;           // 0..2047
        const int k2  = (i & 255) << 1;   // even k
        float x0 = src[row * 512 + k2];
        float x1 = src[row * 512 + k2 + 1];
        uint32_t lp, hp = split_pack(x0, x1, lp);

        const int rb = row >> 4, r = row & 15;
        const int ks = k2 >> 4, kk = k2 & 15;
        const int tg = (kk >> 1) & 3;
        const int s  = ((kk >> 3) << 1) | (r >> 3);    // fragment slot a0..a3
        const int lane = ((r & 7) << 2) | tg;
        const int idx4 = (rb * 32 + ks) * 32 + lane;
        dh[idx4 * 4 + s] = hp;
        dl[idx4 * 4 + s] = lp;
    } else {
        if (i >= U_ * DQ_ / 2) return;
        const float* src = (z == 3) ? W2 : W1;         // [512][256]
        uint32_t* dw = (uint32_t*)g_Wp[z - 2];
        const int n  = i & 255;
        const int k2 = (i >> 8) << 1;
        float x0 = src[k2 * 256 + n];
        float x1 = src[(k2 + 1) * 256 + n];
        uint32_t lp, hp = split_pack(x0, x1, lp);

        const int nb = n >> 3, g = n & 7;
        const int ks = k2 >> 4, kk = k2 & 15;
        const int tg = (kk >> 1) & 3;
        const int bslot = kk >> 3;
        const int lane = (g << 2) | tg;
        const int idx4 = (nb * 32 + ks) * 32 + lane;
        dw[idx4 * 4 + bslot]     = hp;
        dw[idx4 * 4 + 2 + bslot] = lp;
    }
}

// ---------------------------------------------------------------------------
// Kernel A (R6 version): tensor-core GEMM via mma.sync (bf16 hi/lo, fp32 acc).
// C[2048,256] = A[2048,512] @ W[512,256] + bias, z=0 -> s1, z=1 -> s2.
// ---------------------------------------------------------------------------
__global__ __launch_bounds__(256) void gemm_mma_kernel(
    const float* __restrict__ b1, const float* __restrict__ b2)
{
    const int tid  = threadIdx.x;
    const int wid  = tid >> 5;
    const int lane = tid & 31;
    const int g    = lane >> 2;
    const int tg   = lane & 3;

    const int z  = blockIdx.z;
    const int m0 = blockIdx.y * 128;
    const int n0 = blockIdx.x * 64;

    const uint4* __restrict__ Ah = g_Ahp[z];
    const uint4* __restrict__ Al = g_Alp[z];
    const uint4* __restrict__ Bp = g_Wp[z];
    float* __restrict__ C            = z ? g_s2 : g_s1;
    const float* __restrict__ bias   = z ? b2 : b1;

    const int warp_m = wid & 3;
    const int warp_n = wid >> 2;
    const int rb0 = (m0 >> 4) + warp_m * 2;
    const int nb0 = (n0 >> 3) + warp_n * 4;

    float acc[2][4][4];
#pragma unroll
    for (int mt = 0; mt < 2; mt++)
#pragma unroll
        for (int nt = 0; nt < 4; nt++)
#pragma unroll
            for (int c = 0; c < 4; c++) acc[mt][nt][c] = 0.f;

#pragma unroll 2
    for (int ks = 0; ks < 32; ks++) {
        uint4 AH[2], AL[2], Bf[4];
#pragma unroll
        for (int mt = 0; mt < 2; mt++) {
            AH[mt] = Ah[((rb0 + mt) * 32 + ks) * 32 + lane];
            AL[mt] = Al[((rb0 + mt) * 32 + ks) * 32 + lane];
        }
#pragma unroll
        for (int nt = 0; nt < 4; nt++)
            Bf[nt] = Bp[((nb0 + nt) * 32 + ks) * 32 + lane];

#pragma unroll
        for (int mt = 0; mt < 2; mt++)
#pragma unroll
            for (int nt = 0; nt < 4; nt++) {
                mma_bf16(acc[mt][nt], (const uint32_t*)&AH[mt], Bf[nt].x, Bf[nt].y);
                mma_bf16(acc[mt][nt], (const uint32_t*)&AH[mt], Bf[nt].z, Bf[nt].w);
                mma_bf16(acc[mt][nt], (const uint32_t*)&AL[mt], Bf[nt].x, Bf[nt].y);
            }
    }

#pragma unroll
    for (int mt = 0; mt < 2; mt++) {
        const int row = m0 + warp_m * 32 + mt * 16 + g;
#pragma unroll
        for (int nt = 0; nt < 4; nt++) {
            const int col = n0 + warp_n * 32 + nt * 8 + tg * 2;
            const float2 bb = *(const float2*)&bias[col];
            float2 o0, o1;
            o0.x = acc[mt][nt][0] + bb.x;
            o0.y = acc[mt][nt][1] + bb.y;
            o1.x = acc[mt][nt][2] + bb.x;
            o1.y = acc[mt][nt][3] + bb.y;
            *(float2*)&C[(size_t)row * U_ + col]       = o0;
            *(float2*)&C[(size_t)(row + 8) * U_ + col] = o1;
        }
    }
}

// ---------------------------------------------------------------------------
// Kernel B (R6 version): score = Vb + sum_u tanh(s1+s2)*Vw, 32x32 tiles.
// ---------------------------------------------------------------------------
__device__ __forceinline__ float tanh_fast(float x) {
    float y;
    asm("tanh.approx.f32 %0, %1;" : "=f"(y) : "f"(x));
    return y;
}

__global__ __launch_bounds__(256) void score_kernel(
    const float* __restrict__ Vw, const float* __restrict__ Vb)
{
    __shared__ float sS1[32][65];
    __shared__ float sS2[32][65];
    __shared__ float sVw[64];

    const int tid = threadIdx.x;
    const int b   = blockIdx.z;
    const int q0  = blockIdx.y * 32;
    const int v0  = blockIdx.x * 32;

    const int tx = tid & 31;
    const int ty = tid >> 5;

    const int lr  = tid >> 4;
    const int lc4 = (tid & 15) << 2;

    float acc[4] = {0.f, 0.f, 0.f, 0.f};

    for (int u0 = 0; u0 < U_; u0 += 64) {
#pragma unroll
        for (int rr = lr; rr < 32; rr += 16) {
            float4 v1 = *(const float4*)&g_s1[((b * SQ_) + q0 + rr) * U_ + u0 + lc4];
            sS1[rr][lc4 + 0] = v1.x; sS1[rr][lc4 + 1] = v1.y;
            sS1[rr][lc4 + 2] = v1.z; sS1[rr][lc4 + 3] = v1.w;
            float4 v2 = *(const float4*)&g_s2[((b * SV_) + v0 + rr) * U_ + u0 + lc4];
            sS2[rr][lc4 + 0] = v2.x; sS2[rr][lc4 + 1] = v2.y;
            sS2[rr][lc4 + 2] = v2.z; sS2[rr][lc4 + 3] = v2.w;
        }
        if (tid < 64) sVw[tid] = Vw[u0 + tid];
        __syncthreads();

#pragma unroll 8
        for (int uu = 0; uu < 64; uu++) {
            float s2v = sS2[tx][uu];
            float vw  = sVw[uu];
#pragma unroll
            for (int i = 0; i < 4; i++) {
                float t = tanh_fast(sS1[ty * 4 + i][uu] + s2v);
                acc[i] = fmaf(t, vw, acc[i]);
            }
        }
        __syncthreads();
    }

    const float vb = Vb[0];
#pragma unroll
    for (int i = 0; i < 4; i++) {
        int q = q0 + ty * 4 + i;
        g_score[((b * SQ_) + q) * SV_ + v0 + tx] = acc[i] + vb;
    }
}

// ---------------------------------------------------------------------------
// Kernel C (fused, measured 20.1us in R7): softmax + context.
// Tile: 32 q x 128 d per block; grid (4 dtile, 4 qtile, 16 b) = 256 blocks.
// ---------------------------------------------------------------------------
__global__ __launch_bounds__(256) void ctx_kernel(
    const float* __restrict__ values,
    float* __restrict__ out_w,
    float* __restrict__ out_ctx)
{
    __shared__ float sW[32][128];
    __shared__ float sV[2][32 * 128];

    const int tid = threadIdx.x;
    const int b   = blockIdx.z;
    const int q0  = blockIdx.y * 32;
    const int d0  = blockIdx.x * 128;

    const float* __restrict__ vsrc = values + (size_t)b * SV_ * DV_ + d0;
    const uint32_t svb = smem_u32(&sV[0][0]);

    // Phase 0: prefetch values chunk 0 (v rows 0..31).
#pragma unroll
    for (int k = 0; k < 4; k++) {
        const int idx = tid + k * 256;
        const int r   = idx >> 5;
        const int c4  = idx & 31;
        cp_async16(svb + (uint32_t)(r * 128 + c4 * 4) * 4,
                   vsrc + (size_t)r * DV_ + c4 * 4);
    }
    CP_COMMIT();

    // Phase 1: load score tile + in-block row softmax.
#pragma unroll
    for (int k = 0; k < 4; k++) {
        const int idx = tid + k * 256;
        const int r   = idx >> 5;
        const int c4  = idx & 31;
        float4 s = *(const float4*)&g_score[((b * SQ_) + q0 + r) * SV_ + (c4 << 2)];
        *(float4*)&sW[r][c4 << 2] = s;
    }
    __syncthreads();

    const int warp = tid >> 5;
    const int lane = tid & 31;
#pragma unroll
    for (int i = 0; i < 4; i++) {
        const int r = warp * 4 + i;
        float sc[4];
#pragma unroll
        for (int j = 0; j < 4; j++) sc[j] = sW[r][lane + 32 * j];
        float m = fmaxf(fmaxf(sc[0], sc[1]), fmaxf(sc[2], sc[3]));
#pragma unroll
        for (int o = 16; o > 0; o >>= 1)
            m = fmaxf(m, __shfl_xor_sync(0xFFFFFFFFu, m, o));
        float e[4], s = 0.f;
#pragma unroll
        for (int j = 0; j < 4; j++) { e[j] = __expf(sc[j] - m); s += e[j]; }
#pragma unroll
        for (int o = 16; o > 0; o >>= 1)
            s += __shfl_xor_sync(0xFFFFFFFFu, s, o);
        float inv = __fdividef(1.f, s);
#pragma unroll
        for (int j = 0; j < 4; j++) {
            float w = e[j] * inv;
            sW[r][lane + 32 * j] = w;
            if (blockIdx.x == 0)
                out_w[((b * SQ_) + q0 + r) * SV_ + lane + 32 * j] = w;
        }
    }

    // Phase 2: context with cp.async double-buffered values chunks.
    const int dg = tid & 31;
    const int qg = tid >> 5;

    float4 acc[4];
#pragma unroll
    for (int i = 0; i < 4; i++) acc[i] = make_float4(0.f, 0.f, 0.f, 0.f);

#pragma unroll
    for (int c = 0; c < 4; c++) {
        CP_WAIT0();
        __syncthreads();

        if (c < 3) {
            const uint32_t nb = svb + (uint32_t)(((c + 1) & 1) * 32 * 128) * 4;
            const float* gsrc = vsrc + (size_t)(c + 1) * 32 * DV_;
#pragma unroll
            for (int k = 0; k < 4; k++) {
                const int idx = tid + k * 256;
                const int r   = idx >> 5;
                const int c4  = idx & 31;
                cp_async16(nb + (uint32_t)(r * 128 + c4 * 4) * 4,
                           gsrc + (size_t)r * DV_ + c4 * 4);
            }
            CP_COMMIT();
        }

        const float* sv = &sV[c & 1][0];
#pragma unroll
        for (int v = 0; v < 32; v++) {
            float4 vv = *(const float4*)&sv[v * 128 + (dg << 2)];
            const int gv = c * 32 + v;
#pragma unroll
            for (int i = 0; i < 4; i++) {
                float w = sW[qg * 4 + i][gv];
                acc[i].x = fmaf(w, vv.x, acc[i].x);
                acc[i].y = fmaf(w, vv.y, acc[i].y);
                acc[i].z = fmaf(w, vv.z, acc[i].z);
                acc[i].w = fmaf(w, vv.w, acc[i].w);
            }
        }
        __syncthreads();
    }

#pragma unroll
    for (int i = 0; i < 4; i++) {
        const int q = q0 + qg * 4 + i;
        *(float4*)&out_ctx[((size_t)(b * SQ_) + q) * DV_ + d0 + (dg << 2)] = acc[i];
    }
}

// ---------------------------------------------------------------------------
extern "C" void kernel_launch(void* const* d_in, const int* in_sizes, int n_in,
                              void* d_out, int out_size)
{
    const float* query  = (const float*)d_in[0];
    const float* values = (const float*)d_in[1];
    const float* W1     = (const float*)d_in[2];
    const float* b1     = (const float*)d_in[3];
    const float* W2     = (const float*)d_in[4];
    const float* b2     = (const float*)d_in[5];
    const float* Vw     = (const float*)d_in[6];
    const float* Vb     = (const float*)d_in[7];

    float* out_ctx = (float*)d_out;                      // [16,128,512]
    float* out_w   = out_ctx + B_ * SQ_ * DV_;           // [16,128,128,1]

    // fp32 -> bf16 hi/lo split into fragment-native packed layouts
    convert_kernel<<<dim3(2048, 4), 256>>>(query, values, W1, W2);

    // tensor-core GEMMs: s1 = q@W1+b1, s2 = v@W2+b2
    gemm_mma_kernel<<<dim3(4, 16, 2), 256>>>(b1, b2);

    // score = reduce_u tanh(s1+s2)*Vw + Vb
    score_kernel<<<dim3(SV_ / 32, SQ_ / 32, B_), 256>>>(Vw, Vb);

    // fused softmax + context
    ctx_kernel<<<dim3(4, 4, 16), 256>>>(values, out_w, out_ctx);
}

// round 9
// speedup vs baseline: 1.5062x; 1.0919x over previous
#include <cuda_runtime.h>
#include <cuda_bf16.h>
#include <cuda_fp16.h>
#include <cstdint>

// Problem constants
#define B_   16
#define SQ_  128
#define SV_  128
#define DQ_  512
#define DV_  512
#define U_   256

// ---------------------------------------------------------------------------
// Scratch (__device__ globals — no allocation APIs allowed)
// ---------------------------------------------------------------------------
__device__ float g_s1[B_ * SQ_ * U_];      // [2048][256]
__device__ float g_s2[B_ * SV_ * U_];      // [2048][256]
__device__ float g_score[B_ * SQ_ * SV_];  // [16][128][128]

// Fragment-native packed operands for the mma.sync GEMMs.
__device__ uint4 g_Ahp[2][128 * 32 * 32];
__device__ uint4 g_Alp[2][128 * 32 * 32];
__device__ uint4 g_Wp [2][ 32 * 32 * 32];

// ---------------------------------------------------------------------------
// Helpers
// ---------------------------------------------------------------------------
__device__ __forceinline__ uint32_t smem_u32(const void* p) {
    uint32_t a;
    asm("{ .reg .u64 t; cvta.to.shared.u64 t, %1; cvt.u32.u64 %0, t; }"
        : "=r"(a) : "l"(p));
    return a;
}
__device__ __forceinline__ void cp_async16(uint32_t s, const void* g) {
    asm volatile("cp.async.cg.shared.global [%0], [%1], 16;" :: "r"(s), "l"(g));
}
#define CP_COMMIT()  asm volatile("cp.async.commit_group;" ::: "memory")
#define CP_WAIT0()   asm volatile("cp.async.wait_group 0;" ::: "memory")

// mma.sync m16n8k16 bf16 (row.col), fp32 accumulate — base sm_80+ feature.
__device__ __forceinline__ void mma_bf16(float* d, const uint32_t* a,
                                         uint32_t b0, uint32_t b1) {
    asm volatile(
        "mma.sync.aligned.m16n8k16.row.col.f32.bf16.bf16.f32 "
        "{%0,%1,%2,%3}, {%4,%5,%6,%7}, {%8,%9}, {%0,%1,%2,%3};"
        : "+f"(d[0]), "+f"(d[1]), "+f"(d[2]), "+f"(d[3])
        : "r"(a[0]), "r"(a[1]), "r"(a[2]), "r"(a[3]), "r"(b0), "r"(b1));
}

__device__ __forceinline__ uint32_t split_pack(float x0, float x1, uint32_t& lo_pack) {
    __nv_bfloat16 h0 = __float2bfloat16(x0);
    __nv_bfloat16 h1 = __float2bfloat16(x1);
    float r0 = x0 - __bfloat162float(h0);
    float r1 = x1 - __bfloat162float(h1);
    __nv_bfloat16 l0 = __float2bfloat16(r0);
    __nv_bfloat16 l1 = __float2bfloat16(r1);
    lo_pack = ((uint32_t)__bfloat16_as_ushort(l1) << 16) | __bfloat16_as_ushort(l0);
    return ((uint32_t)__bfloat16_as_ushort(h1) << 16) | __bfloat16_as_ushort(h0);
}

// ---------------------------------------------------------------------------
// Kernel 0 (R7 vectorized version — numerically verified identical):
// fp32 -> bf16 (hi, lo) split; each thread emits COMPLETE uint4 fragments.
// grid (512, 4): y=0 query, y=1 values, y=2 W1, y=3 W2.
// ---------------------------------------------------------------------------
__global__ __launch_bounds__(256) void convert_kernel(
    const float* __restrict__ q, const float* __restrict__ v,
    const float* __restrict__ W1, const float* __restrict__ W2)
{
    const int z = blockIdx.y;
    const int j = blockIdx.x * 256 + threadIdx.x;

    if (z < 2) {
        const float* __restrict__ src = z ? v : q;       // [2048][512]
        const int rb   = j >> 10;            // 0..127
        const int ks   = (j >> 5) & 31;      // 0..31
        const int lane = j & 31;
        const int r0 = rb * 16 + (lane >> 2);
        const int k0 = ks * 16 + (lane & 3) * 2;

        float2 a00 = *(const float2*)&src[(size_t)r0 * 512 + k0];
        float2 a01 = *(const float2*)&src[(size_t)r0 * 512 + k0 + 8];
        float2 a10 = *(const float2*)&src[(size_t)(r0 + 8) * 512 + k0];
        float2 a11 = *(const float2*)&src[(size_t)(r0 + 8) * 512 + k0 + 8];

        uint4 hi, lo;
        hi.x = split_pack(a00.x, a00.y, lo.x);
        hi.y = split_pack(a10.x, a10.y, lo.y);
        hi.z = split_pack(a01.x, a01.y, lo.z);
        hi.w = split_pack(a11.x, a11.y, lo.w);
        g_Ahp[z][j] = hi;
        g_Alp[z][j] = lo;
    } else {
        if (j >= 32 * 32 * 32) return;
        const float* __restrict__ src = (z == 3) ? W2 : W1;  // [512][256]
        const int nb   = j >> 10;            // 0..31
        const int ks   = (j >> 5) & 31;
        const int lane = j & 31;
        const int n  = nb * 8 + (lane >> 2);
        const int k0 = ks * 16 + (lane & 3) * 2;

        float w00 = src[(size_t)k0 * 256 + n];
        float w01 = src[(size_t)(k0 + 1) * 256 + n];
        float w10 = src[(size_t)(k0 + 8) * 256 + n];
        float w11 = src[(size_t)(k0 + 9) * 256 + n];

        uint4 f;
        uint32_t l0, l1;
        f.x = split_pack(w00, w01, l0);
        f.y = split_pack(w10, w11, l1);
        f.z = l0;
        f.w = l1;
        g_Wp[z - 2][j] = f;
    }
}

// ---------------------------------------------------------------------------
// Kernel A (R6/R8 version): tensor-core GEMM via mma.sync.
// ---------------------------------------------------------------------------
__global__ __launch_bounds__(256) void gemm_mma_kernel(
    const float* __restrict__ b1, const float* __restrict__ b2)
{
    const int tid  = threadIdx.x;
    const int wid  = tid >> 5;
    const int lane = tid & 31;
    const int g    = lane >> 2;
    const int tg   = lane & 3;

    const int z  = blockIdx.z;
    const int m0 = blockIdx.y * 128;
    const int n0 = blockIdx.x * 64;

    const uint4* __restrict__ Ah = g_Ahp[z];
    const uint4* __restrict__ Al = g_Alp[z];
    const uint4* __restrict__ Bp = g_Wp[z];
    float* __restrict__ C            = z ? g_s2 : g_s1;
    const float* __restrict__ bias   = z ? b2 : b1;

    const int warp_m = wid & 3;
    const int warp_n = wid >> 2;
    const int rb0 = (m0 >> 4) + warp_m * 2;
    const int nb0 = (n0 >> 3) + warp_n * 4;

    float acc[2][4][4];
#pragma unroll
    for (int mt = 0; mt < 2; mt++)
#pragma unroll
        for (int nt = 0; nt < 4; nt++)
#pragma unroll
            for (int c = 0; c < 4; c++) acc[mt][nt][c] = 0.f;

#pragma unroll 2
    for (int ks = 0; ks < 32; ks++) {
        uint4 AH[2], AL[2], Bf[4];
#pragma unroll
        for (int mt = 0; mt < 2; mt++) {
            AH[mt] = Ah[((rb0 + mt) * 32 + ks) * 32 + lane];
            AL[mt] = Al[((rb0 + mt) * 32 + ks) * 32 + lane];
        }
#pragma unroll
        for (int nt = 0; nt < 4; nt++)
            Bf[nt] = Bp[((nb0 + nt) * 32 + ks) * 32 + lane];

#pragma unroll
        for (int mt = 0; mt < 2; mt++)
#pragma unroll
            for (int nt = 0; nt < 4; nt++) {
                mma_bf16(acc[mt][nt], (const uint32_t*)&AH[mt], Bf[nt].x, Bf[nt].y);
                mma_bf16(acc[mt][nt], (const uint32_t*)&AH[mt], Bf[nt].z, Bf[nt].w);
                mma_bf16(acc[mt][nt], (const uint32_t*)&AL[mt], Bf[nt].x, Bf[nt].y);
            }
    }

#pragma unroll
    for (int mt = 0; mt < 2; mt++) {
        const int row = m0 + warp_m * 32 + mt * 16 + g;
#pragma unroll
        for (int nt = 0; nt < 4; nt++) {
            const int col = n0 + warp_n * 32 + nt * 8 + tg * 2;
            const float2 bb = *(const float2*)&bias[col];
            float2 o0, o1;
            o0.x = acc[mt][nt][0] + bb.x;
            o0.y = acc[mt][nt][1] + bb.y;
            o1.x = acc[mt][nt][2] + bb.x;
            o1.y = acc[mt][nt][3] + bb.y;
            *(float2*)&C[(size_t)row * U_ + col]       = o0;
            *(float2*)&C[(size_t)(row + 8) * U_ + col] = o1;
        }
    }
}

// ---------------------------------------------------------------------------
// Kernel B: score via tanh.approx.f16x2 — 2 tanh per MUFU op.
// s1/s2 staged in smem as f16x2 pairs over adjacent u; fp32 accumulation.
// 32q x 32v tiles, 256 blocks (same shape as the known-good R6 kernel).
// ---------------------------------------------------------------------------
__global__ __launch_bounds__(256) void score_kernel(
    const float* __restrict__ Vw, const float* __restrict__ Vb)
{
    __shared__ uint32_t sS1[32][33];   // 32 rows x 32 f16x2 pairs (64 u), +1 pad
    __shared__ uint32_t sS2[32][33];
    __shared__ float    sVw[64];

    const int tid = threadIdx.x;
    const int b   = blockIdx.z;
    const int q0  = blockIdx.y * 32;
    const int v0  = blockIdx.x * 32;

    const int tx = tid & 31;        // v lane
    const int ty = tid >> 5;        // q group (4 rows)

    const int lr  = tid >> 4;       // 0..15
    const int lc4 = (tid & 15) << 2;  // float4 col in 64-u chunk
    const int lp  = lc4 >> 1;         // pair index (2 pairs per float4)

    float acc[4] = {0.f, 0.f, 0.f, 0.f};

    for (int u0 = 0; u0 < U_; u0 += 64) {
#pragma unroll
        for (int rr = lr; rr < 32; rr += 16) {
            float4 v1 = *(const float4*)&g_s1[((b * SQ_) + q0 + rr) * U_ + u0 + lc4];
            __half2 p0 = __floats2half2_rn(v1.x, v1.y);
            __half2 p1 = __floats2half2_rn(v1.z, v1.w);
            sS1[rr][lp]     = *(uint32_t*)&p0;
            sS1[rr][lp + 1] = *(uint32_t*)&p1;
            float4 v2 = *(const float4*)&g_s2[((b * SV_) + v0 + rr) * U_ + u0 + lc4];
            __half2 r0 = __floats2half2_rn(v2.x, v2.y);
            __half2 r1 = __floats2half2_rn(v2.z, v2.w);
            sS2[rr][lp]     = *(uint32_t*)&r0;
            sS2[rr][lp + 1] = *(uint32_t*)&r1;
        }
        if (tid < 64) sVw[tid] = Vw[u0 + tid];
        __syncthreads();

#pragma unroll 8
        for (int uu = 0; uu < 32; uu++) {          // 32 pairs = 64 u
            const uint32_t s2p = sS2[tx][uu];
            const float vw0 = sVw[2 * uu];
            const float vw1 = sVw[2 * uu + 1];
#pragma unroll
            for (int i = 0; i < 4; i++) {
                const uint32_t ap = sS1[ty * 4 + i][uu];   // broadcast
                __half2 sum = __hadd2(*(const __half2*)&ap, *(const __half2*)&s2p);
                uint32_t t;
                asm("tanh.approx.f16x2 %0, %1;"
                    : "=r"(t) : "r"(*(const uint32_t*)&sum));
                float2 tf = __half22float2(*(const __half2*)&t);
                acc[i] = fmaf(tf.x, vw0, acc[i]);
                acc[i] = fmaf(tf.y, vw1, acc[i]);
            }
        }
        __syncthreads();
    }

    const float vb = Vb[0];
#pragma unroll
    for (int i = 0; i < 4; i++) {
        int q = q0 + ty * 4 + i;
        g_score[((b * SQ_) + q) * SV_ + v0 + tx] = acc[i] + vb;
    }
}

// ---------------------------------------------------------------------------
// Kernel C (R8 fused version): softmax + context.
// ---------------------------------------------------------------------------
__global__ __launch_bounds__(256) void ctx_kernel(
    const float* __restrict__ values,
    float* __restrict__ out_w,
    float* __restrict__ out_ctx)
{
    __shared__ float sW[32][128];
    __shared__ float sV[2][32 * 128];

    const int tid = threadIdx.x;
    const int b   = blockIdx.z;
    const int q0  = blockIdx.y * 32;
    const int d0  = blockIdx.x * 128;

    const float* __restrict__ vsrc = values + (size_t)b * SV_ * DV_ + d0;
    const uint32_t svb = smem_u32(&sV[0][0]);

#pragma unroll
    for (int k = 0; k < 4; k++) {
        const int idx = tid + k * 256;
        const int r   = idx >> 5;
        const int c4  = idx & 31;
        cp_async16(svb + (uint32_t)(r * 128 + c4 * 4) * 4,
                   vsrc + (size_t)r * DV_ + c4 * 4);
    }
    CP_COMMIT();

#pragma unroll
    for (int k = 0; k < 4; k++) {
        const int idx = tid + k * 256;
        const int r   = idx >> 5;
        const int c4  = idx & 31;
        float4 s = *(const float4*)&g_score[((b * SQ_) + q0 + r) * SV_ + (c4 << 2)];
        *(float4*)&sW[r][c4 << 2] = s;
    }
    __syncthreads();

    const int warp = tid >> 5;
    const int lane = tid & 31;
#pragma unroll
    for (int i = 0; i < 4; i++) {
        const int r = warp * 4 + i;
        float sc[4];
#pragma unroll
        for (int j = 0; j < 4; j++) sc[j] = sW[r][lane + 32 * j];
        float m = fmaxf(fmaxf(sc[0], sc[1]), fmaxf(sc[2], sc[3]));
#pragma unroll
        for (int o = 16; o > 0; o >>= 1)
            m = fmaxf(m, __shfl_xor_sync(0xFFFFFFFFu, m, o));
        float e[4], s = 0.f;
#pragma unroll
        for (int j = 0; j < 4; j++) { e[j] = __expf(sc[j] - m); s += e[j]; }
#pragma unroll
        for (int o = 16; o > 0; o >>= 1)
            s += __shfl_xor_sync(0xFFFFFFFFu, s, o);
        float inv = __fdividef(1.f, s);
#pragma unroll
        for (int j = 0; j < 4; j++) {
            float w = e[j] * inv;
            sW[r][lane + 32 * j] = w;
            if (blockIdx.x == 0)
                out_w[((b * SQ_) + q0 + r) * SV_ + lane + 32 * j] = w;
        }
    }

    const int dg = tid & 31;
    const int qg = tid >> 5;

    float4 acc[4];
#pragma unroll
    for (int i = 0; i < 4; i++) acc[i] = make_float4(0.f, 0.f, 0.f, 0.f);

#pragma unroll
    for (int c = 0; c < 4; c++) {
        CP_WAIT0();
        __syncthreads();

        if (c < 3) {
            const uint32_t nb = svb + (uint32_t)(((c + 1) & 1) * 32 * 128) * 4;
            const float* gsrc = vsrc + (size_t)(c + 1) * 32 * DV_;
#pragma unroll
            for (int k = 0; k < 4; k++) {
                const int idx = tid + k * 256;
                const int r   = idx >> 5;
                const int c4  = idx & 31;
                cp_async16(nb + (uint32_t)(r * 128 + c4 * 4) * 4,
                           gsrc + (size_t)r * DV_ + c4 * 4);
            }
            CP_COMMIT();
        }

        const float* sv = &sV[c & 1][0];
#pragma unroll
        for (int v = 0; v < 32; v++) {
            float4 vv = *(const float4*)&sv[v * 128 + (dg << 2)];
            const int gv = c * 32 + v;
#pragma unroll
            for (int i = 0; i < 4; i++) {
                float w = sW[qg * 4 + i][gv];
                acc[i].x = fmaf(w, vv.x, acc[i].x);
                acc[i].y = fmaf(w, vv.y, acc[i].y);
                acc[i].z = fmaf(w, vv.z, acc[i].z);
                acc[i].w = fmaf(w, vv.w, acc[i].w);
            }
        }
        __syncthreads();
    }

#pragma unroll
    for (int i = 0; i < 4; i++) {
        const int q = q0 + qg * 4 + i;
        *(float4*)&out_ctx[((size_t)(b * SQ_) + q) * DV_ + d0 + (dg << 2)] = acc[i];
    }
}

// ---------------------------------------------------------------------------
extern "C" void kernel_launch(void* const* d_in, const int* in_sizes, int n_in,
                              void* d_out, int out_size)
{
    const float* query  = (const float*)d_in[0];
    const float* values = (const float*)d_in[1];
    const float* W1     = (const float*)d_in[2];
    const float* b1     = (const float*)d_in[3];
    const float* W2     = (const float*)d_in[4];
    const float* b2     = (const float*)d_in[5];
    const float* Vw     = (const float*)d_in[6];
    const float* Vb     = (const float*)d_in[7];

    float* out_ctx = (float*)d_out;                      // [16,128,512]
    float* out_w   = out_ctx + B_ * SQ_ * DV_;           // [16,128,128,1]

    // fp32 -> bf16 hi/lo split into fragment-native packed layouts
    convert_kernel<<<dim3(512, 4), 256>>>(query, values, W1, W2);

    // tensor-core GEMMs: s1 = q@W1+b1, s2 = v@W2+b2
    gemm_mma_kernel<<<dim3(4, 16, 2), 256>>>(b1, b2);

    // score = reduce_u tanh(s1+s2)*Vw + Vb  (f16x2 MUFU path)
    score_kernel<<<dim3(SV_ / 32, SQ_ / 32, B_), 256>>>(Vw, Vb);

    // fused softmax + context
    ctx_kernel<<<dim3(4, 4, 16), 256>>>(values, out_w, out_ctx);
}